// round 1
// baseline (speedup 1.0000x reference)
#include <cuda_runtime.h>

#define NNODES 50000
#define NEDGES 800000
#define DD 32

// scratch for segment_sum (allowed: __device__ global)
__device__ float g_node_tmp[NNODES * DD];

__global__ void zero_tmp_kernel() {
    int i = blockIdx.x * blockDim.x + threadIdx.x;
    if (i < NNODES * DD) g_node_tmp[i] = 0.0f;
}

// ---------------------------------------------------------------------------
// Edge kernel: TE=64 edges per block, 256 threads.
// Pipeline per tile:
//   gather  sA=[he|hn_src|hn_dst] (64x96), sF=[pos_s|pos_d|fes|0,0] (64x24)
//   G1: H1 = relu(sA @ ev_w1)         64x96 @ 96x128
//   G2: V  = H1 @ ev_w2               64x128 @ 128x16
//   G3: H2 = relu(sF @ fc_w1)         64x22 @ 22x64
//   G4: tp = P @ fc_w2'               64x1024 @ 1024x32,
//       where P[e,(k,v)] = H2[e,k]*V[e,v] formed on the fly and
//       fc_w2 (64,512) row-major IS (1024,32) row-major under kk=k*16+v.
//   epilogue: hen = he + tp -> out ; atomicAdd(node_tmp[dst], hen*norm)
// ---------------------------------------------------------------------------

// smem float offsets
#define OFF_A    0        // 64 x 97   = 6208
#define OFF_F    6208     // 64 x 24   = 1536
#define OFF_H1   7744     // 64 x 132  = 8448
#define OFF_V    16192    // 64 x 20   = 1280
#define OFF_H2   17472    // 64 x 68   = 4352
#define OFF_WT   21824    // 4096 (16KB weight tile)
#define OFF_SRC  25920    // 64 int
#define OFF_DST  25984    // 64 int
#define OFF_NRM  26048    // 64 float
#define EDGE_SMEM_FLOATS 26112
#define EDGE_SMEM_BYTES  (EDGE_SMEM_FLOATS * 4)

__global__ __launch_bounds__(256, 2)
void edge_kernel(const float* __restrict__ hn, const float* __restrict__ he,
                 const float* __restrict__ pos, const float* __restrict__ fes,
                 const float* __restrict__ norm,
                 const int* __restrict__ esrc, const int* __restrict__ edst,
                 const float* __restrict__ ev_w1, const float* __restrict__ ev_w2,
                 const float* __restrict__ fc_w1, const float* __restrict__ fc_w2,
                 float* __restrict__ out_hen)
{
    extern __shared__ float sm[];
    float* sA   = sm + OFF_A;
    float* sF   = sm + OFF_F;
    float* sH1  = sm + OFF_H1;
    float* sV   = sm + OFF_V;
    float* sH2  = sm + OFF_H2;
    float* sWT  = sm + OFF_WT;
    int*   sSrc = (int*)(sm + OFF_SRC);
    int*   sDst = (int*)(sm + OFF_DST);
    float* sNrm = sm + OFF_NRM;

    const int tid = threadIdx.x;
    const int e0  = blockIdx.x * 64;

    if (tid < 64) {
        int ge = e0 + tid;
        sSrc[tid] = esrc[ge];
        sDst[tid] = edst[ge];
        sNrm[tid] = norm[ge];
    }
    __syncthreads();

    // ---- gather phase ----
    for (int i = tid; i < 64 * 96; i += 256) {
        int e = i / 96, k = i - e * 96;
        float v;
        if (k < 32)      v = he[(size_t)(e0 + e) * 32 + k];
        else if (k < 64) v = hn[(size_t)sSrc[e] * 32 + (k - 32)];
        else             v = hn[(size_t)sDst[e] * 32 + (k - 64)];
        sA[e * 97 + k] = v;
    }
    for (int i = tid; i < 64 * 24; i += 256) {
        int e = i / 24, k = i - e * 24;
        float v = 0.0f;
        if (k < 3)       v = pos[(size_t)sSrc[e] * 3 + k];
        else if (k < 6)  v = pos[(size_t)sDst[e] * 3 + (k - 3)];
        else if (k < 22) v = fes[(size_t)(e0 + e) * 16 + (k - 6)];
        sF[e * 24 + k] = v;
    }

    // ---- G1: H1 = relu(sA @ ev_w1)  (64x96 @ 96x128) ----
    {
        const int eg = tid >> 4, mg = tid & 15;
        const int el = eg * 4, m0 = mg * 8;
        float acc[4][8];
        #pragma unroll
        for (int i = 0; i < 4; i++)
            #pragma unroll
            for (int j = 0; j < 8; j++) acc[i][j] = 0.0f;

        for (int kt = 0; kt < 96; kt += 32) {
            __syncthreads();
            #pragma unroll
            for (int i = tid * 4; i < 4096; i += 1024)
                *(float4*)&sWT[i] = *(const float4*)&ev_w1[kt * 128 + i];
            __syncthreads();
            #pragma unroll 8
            for (int kk = 0; kk < 32; kk++) {
                float a0 = sA[(el + 0) * 97 + kt + kk];
                float a1 = sA[(el + 1) * 97 + kt + kk];
                float a2 = sA[(el + 2) * 97 + kt + kk];
                float a3 = sA[(el + 3) * 97 + kt + kk];
                float4 b0 = *(float4*)&sWT[kk * 128 + m0];
                float4 b1 = *(float4*)&sWT[kk * 128 + m0 + 4];
                float bb[8] = {b0.x, b0.y, b0.z, b0.w, b1.x, b1.y, b1.z, b1.w};
                #pragma unroll
                for (int j = 0; j < 8; j++) {
                    acc[0][j] += a0 * bb[j];
                    acc[1][j] += a1 * bb[j];
                    acc[2][j] += a2 * bb[j];
                    acc[3][j] += a3 * bb[j];
                }
            }
        }
        #pragma unroll
        for (int i = 0; i < 4; i++) {
            float4 r0 = make_float4(fmaxf(acc[i][0], 0.f), fmaxf(acc[i][1], 0.f),
                                    fmaxf(acc[i][2], 0.f), fmaxf(acc[i][3], 0.f));
            float4 r1 = make_float4(fmaxf(acc[i][4], 0.f), fmaxf(acc[i][5], 0.f),
                                    fmaxf(acc[i][6], 0.f), fmaxf(acc[i][7], 0.f));
            *(float4*)&sH1[(el + i) * 132 + m0]     = r0;
            *(float4*)&sH1[(el + i) * 132 + m0 + 4] = r1;
        }
    }

    // ---- G2: V = H1 @ ev_w2  (64x128 @ 128x16) ----
    {
        __syncthreads();
        #pragma unroll
        for (int i = tid * 4; i < 2048; i += 1024)
            *(float4*)&sWT[i] = *(const float4*)&ev_w2[i];
        __syncthreads();
        const int e = tid >> 2, m0 = (tid & 3) * 4;
        float a4[4] = {0.f, 0.f, 0.f, 0.f};
        #pragma unroll 8
        for (int k = 0; k < 128; k++) {
            float a = sH1[e * 132 + k];
            float4 b = *(float4*)&sWT[k * 16 + m0];
            a4[0] += a * b.x; a4[1] += a * b.y; a4[2] += a * b.z; a4[3] += a * b.w;
        }
        *(float4*)&sV[e * 20 + m0] = make_float4(a4[0], a4[1], a4[2], a4[3]);
    }

    // ---- G3: H2 = relu(sF @ fc_w1)  (64x22 @ 22x64) ----
    {
        __syncthreads();
        for (int i = tid; i < 22 * 64; i += 256) sWT[i] = fc_w1[i];
        __syncthreads();
        const int eg = tid >> 4, mg = tid & 15;
        const int el = eg * 4, m0 = mg * 4;
        float acc[4][4];
        #pragma unroll
        for (int i = 0; i < 4; i++)
            #pragma unroll
            for (int j = 0; j < 4; j++) acc[i][j] = 0.0f;
        #pragma unroll
        for (int k = 0; k < 22; k++) {
            float a0 = sF[(el + 0) * 24 + k];
            float a1 = sF[(el + 1) * 24 + k];
            float a2 = sF[(el + 2) * 24 + k];
            float a3 = sF[(el + 3) * 24 + k];
            float4 b = *(float4*)&sWT[k * 64 + m0];
            acc[0][0] += a0 * b.x; acc[0][1] += a0 * b.y; acc[0][2] += a0 * b.z; acc[0][3] += a0 * b.w;
            acc[1][0] += a1 * b.x; acc[1][1] += a1 * b.y; acc[1][2] += a1 * b.z; acc[1][3] += a1 * b.w;
            acc[2][0] += a2 * b.x; acc[2][1] += a2 * b.y; acc[2][2] += a2 * b.z; acc[2][3] += a2 * b.w;
            acc[3][0] += a3 * b.x; acc[3][1] += a3 * b.y; acc[3][2] += a3 * b.z; acc[3][3] += a3 * b.w;
        }
        #pragma unroll
        for (int i = 0; i < 4; i++) {
            float4 r = make_float4(fmaxf(acc[i][0], 0.f), fmaxf(acc[i][1], 0.f),
                                   fmaxf(acc[i][2], 0.f), fmaxf(acc[i][3], 0.f));
            *(float4*)&sH2[(el + i) * 68 + m0] = r;
        }
    }

    // ---- G4: tp = P @ fc_w2'  (64x1024 @ 1024x32), P on the fly ----
    {
        __syncthreads();   // sH2, sV complete; sWT free
        const int e = tid >> 2, m0 = (tid & 3) * 8;
        float vreg[16];
        #pragma unroll
        for (int v = 0; v < 16; v++) vreg[v] = sV[e * 20 + v];
        float acc[8];
        #pragma unroll
        for (int j = 0; j < 8; j++) acc[j] = 0.0f;

        for (int kt = 0; kt < 1024; kt += 128) {
            __syncthreads();
            #pragma unroll
            for (int i = tid * 4; i < 4096; i += 1024)
                *(float4*)&sWT[i] = *(const float4*)&fc_w2[kt * 32 + i];
            __syncthreads();
            const int k2b = kt >> 4;
            #pragma unroll 2
            for (int k2l = 0; k2l < 8; k2l++) {
                float h = sH2[e * 68 + k2b + k2l];
                #pragma unroll
                for (int v = 0; v < 16; v++) {
                    float a = h * vreg[v];
                    int kk = k2l * 16 + v;
                    float4 b0 = *(float4*)&sWT[kk * 32 + m0];
                    float4 b1 = *(float4*)&sWT[kk * 32 + m0 + 4];
                    acc[0] += a * b0.x; acc[1] += a * b0.y;
                    acc[2] += a * b0.z; acc[3] += a * b0.w;
                    acc[4] += a * b1.x; acc[5] += a * b1.y;
                    acc[6] += a * b1.z; acc[7] += a * b1.w;
                }
            }
        }

        // epilogue: hen = he + tp ; write out ; scatter-add hen*norm
        const int ge = e0 + e;
        float4 h0 = *(const float4*)&he[(size_t)ge * 32 + m0];
        float4 h1 = *(const float4*)&he[(size_t)ge * 32 + m0 + 4];
        float r[8];
        r[0] = h0.x + acc[0]; r[1] = h0.y + acc[1];
        r[2] = h0.z + acc[2]; r[3] = h0.w + acc[3];
        r[4] = h1.x + acc[4]; r[5] = h1.y + acc[5];
        r[6] = h1.z + acc[6]; r[7] = h1.w + acc[7];
        *(float4*)&out_hen[(size_t)ge * 32 + m0]     = make_float4(r[0], r[1], r[2], r[3]);
        *(float4*)&out_hen[(size_t)ge * 32 + m0 + 4] = make_float4(r[4], r[5], r[6], r[7]);

        const float nrm = sNrm[e];
        float* dp = &g_node_tmp[(size_t)sDst[e] * 32 + m0];
        #pragma unroll
        for (int j = 0; j < 8; j++) atomicAdd(dp + j, r[j] * nrm);
    }
}

// ---------------------------------------------------------------------------
// Node kernel: TN=64 nodes per block, 256 threads.
//   sX = [hn | node_tmp] (64x64), G5: relu(sX @ nu_w1) (64x128),
//   G6: @ nu_w2 (128x32), hnn = hn + out.
// ---------------------------------------------------------------------------
#define NOFF_X  0        // 64 x 68 = 4352
#define NOFF_H  4352     // 64 x 132 = 8448
#define NOFF_W  12800    // 8192 (32KB)
#define NODE_SMEM_FLOATS 20992
#define NODE_SMEM_BYTES  (NODE_SMEM_FLOATS * 4)

__global__ __launch_bounds__(256, 2)
void node_kernel(const float* __restrict__ hn,
                 const float* __restrict__ nu_w1, const float* __restrict__ nu_w2,
                 float* __restrict__ out_hnn)
{
    extern __shared__ float sm[];
    float* sX = sm + NOFF_X;
    float* sH = sm + NOFF_H;
    float* sW = sm + NOFF_W;
    const int tid = threadIdx.x;
    const int n0  = blockIdx.x * 64;

    for (int i = tid; i < 64 * 64; i += 256) {
        int e = i >> 6, k = i & 63;
        int gn = n0 + e;
        float v = 0.0f;
        if (gn < NNODES)
            v = (k < 32) ? hn[(size_t)gn * 32 + k] : g_node_tmp[(size_t)gn * 32 + (k - 32)];
        sX[e * 68 + k] = v;
    }
    #pragma unroll
    for (int i = tid * 4; i < 8192; i += 1024)
        *(float4*)&sW[i] = *(const float4*)&nu_w1[i];
    __syncthreads();

    // G5: relu(sX @ nu_w1)  (64x64 @ 64x128)
    {
        const int eg = tid >> 4, mg = tid & 15;
        const int el = eg * 4, m0 = mg * 8;
        float acc[4][8];
        #pragma unroll
        for (int i = 0; i < 4; i++)
            #pragma unroll
            for (int j = 0; j < 8; j++) acc[i][j] = 0.0f;
        #pragma unroll 4
        for (int k = 0; k < 64; k++) {
            float a0 = sX[(el + 0) * 68 + k];
            float a1 = sX[(el + 1) * 68 + k];
            float a2 = sX[(el + 2) * 68 + k];
            float a3 = sX[(el + 3) * 68 + k];
            float4 b0 = *(float4*)&sW[k * 128 + m0];
            float4 b1 = *(float4*)&sW[k * 128 + m0 + 4];
            float bb[8] = {b0.x, b0.y, b0.z, b0.w, b1.x, b1.y, b1.z, b1.w};
            #pragma unroll
            for (int j = 0; j < 8; j++) {
                acc[0][j] += a0 * bb[j];
                acc[1][j] += a1 * bb[j];
                acc[2][j] += a2 * bb[j];
                acc[3][j] += a3 * bb[j];
            }
        }
        #pragma unroll
        for (int i = 0; i < 4; i++) {
            float4 r0 = make_float4(fmaxf(acc[i][0], 0.f), fmaxf(acc[i][1], 0.f),
                                    fmaxf(acc[i][2], 0.f), fmaxf(acc[i][3], 0.f));
            float4 r1 = make_float4(fmaxf(acc[i][4], 0.f), fmaxf(acc[i][5], 0.f),
                                    fmaxf(acc[i][6], 0.f), fmaxf(acc[i][7], 0.f));
            *(float4*)&sH[(el + i) * 132 + m0]     = r0;
            *(float4*)&sH[(el + i) * 132 + m0 + 4] = r1;
        }
    }
    __syncthreads();
    #pragma unroll
    for (int i = tid * 4; i < 4096; i += 1024)
        *(float4*)&sW[i] = *(const float4*)&nu_w2[i];
    __syncthreads();

    // G6: (64x128 @ 128x32) + residual
    {
        const int e = tid >> 2, m0 = (tid & 3) * 8;
        float acc[8];
        #pragma unroll
        for (int j = 0; j < 8; j++) acc[j] = 0.0f;
        #pragma unroll 4
        for (int k = 0; k < 128; k++) {
            float a = sH[e * 132 + k];
            float4 b0 = *(float4*)&sW[k * 32 + m0];
            float4 b1 = *(float4*)&sW[k * 32 + m0 + 4];
            acc[0] += a * b0.x; acc[1] += a * b0.y;
            acc[2] += a * b0.z; acc[3] += a * b0.w;
            acc[4] += a * b1.x; acc[5] += a * b1.y;
            acc[6] += a * b1.z; acc[7] += a * b1.w;
        }
        const int gn = n0 + e;
        if (gn < NNODES) {
            float4 h0 = *(const float4*)&hn[(size_t)gn * 32 + m0];
            float4 h1 = *(const float4*)&hn[(size_t)gn * 32 + m0 + 4];
            *(float4*)&out_hnn[(size_t)gn * 32 + m0] =
                make_float4(h0.x + acc[0], h0.y + acc[1], h0.z + acc[2], h0.w + acc[3]);
            *(float4*)&out_hnn[(size_t)gn * 32 + m0 + 4] =
                make_float4(h1.x + acc[4], h1.y + acc[5], h1.z + acc[6], h1.w + acc[7]);
        }
    }
}

extern "C" void kernel_launch(void* const* d_in, const int* in_sizes, int n_in,
                              void* d_out, int out_size)
{
    const float* hn    = (const float*)d_in[0];
    const float* he    = (const float*)d_in[1];
    const float* pos   = (const float*)d_in[2];
    const float* fes   = (const float*)d_in[3];
    const float* norm  = (const float*)d_in[4];
    const int*   esrc  = (const int*)d_in[5];
    const int*   edst  = (const int*)d_in[6];
    const float* ev_w1 = (const float*)d_in[7];
    const float* ev_w2 = (const float*)d_in[8];
    const float* fc_w1 = (const float*)d_in[9];
    const float* fc_w2 = (const float*)d_in[10];
    const float* nu_w1 = (const float*)d_in[11];
    const float* nu_w2 = (const float*)d_in[12];

    float* out     = (float*)d_out;
    float* out_hnn = out;                               // [N, 32]
    float* out_hen = out + (size_t)NNODES * 32;         // [E, 32]

    cudaFuncSetAttribute(edge_kernel, cudaFuncAttributeMaxDynamicSharedMemorySize,
                         EDGE_SMEM_BYTES);
    cudaFuncSetAttribute(node_kernel, cudaFuncAttributeMaxDynamicSharedMemorySize,
                         NODE_SMEM_BYTES);

    zero_tmp_kernel<<<(NNODES * DD + 255) / 256, 256>>>();
    edge_kernel<<<NEDGES / 64, 256, EDGE_SMEM_BYTES>>>(
        hn, he, pos, fes, norm, esrc, edst,
        ev_w1, ev_w2, fc_w1, fc_w2, out_hen);
    node_kernel<<<(NNODES + 63) / 64, 256, NODE_SMEM_BYTES>>>(
        hn, nu_w1, nu_w2, out_hnn);
}

// round 2
// speedup vs baseline: 1.0007x; 1.0007x over previous
#include <cuda_runtime.h>

#define NNODES 50000
#define NEDGES 800000
#define DD 32

// scratch for segment_sum (allowed: __device__ global)
__device__ float g_node_tmp[NNODES * DD];

__global__ void zero_tmp_kernel() {
    int i = blockIdx.x * blockDim.x + threadIdx.x;
    if (i < NNODES * DD) g_node_tmp[i] = 0.0f;
}

// ---------------------------------------------------------------------------
// Edge kernel: TE=64 edges per block, 256 threads.
// Pipeline per tile:
//   gather  sA=[he|hn_src|hn_dst] (64x96), sF=[pos_s|pos_d|fes|0,0] (64x24)
//   G1: H1 = relu(sA @ ev_w1)         64x96 @ 96x128
//   G2: V  = H1 @ ev_w2               64x128 @ 128x16
//   G3: H2 = relu(sF @ fc_w1)         64x22 @ 22x64
//   G4: tp = P @ fc_w2'               64x1024 @ 1024x32,
//       where P[e,(k,v)] = H2[e,k]*V[e,v] formed on the fly and
//       fc_w2 (64,512) row-major IS (1024,32) row-major under kk=k*16+v.
//   epilogue: hen = he + tp -> out ; atomicAdd(node_tmp[dst], hen*norm)
// ---------------------------------------------------------------------------

// smem float offsets
#define OFF_A    0        // 64 x 97   = 6208
#define OFF_F    6208     // 64 x 24   = 1536
#define OFF_H1   7744     // 64 x 132  = 8448
#define OFF_V    16192    // 64 x 20   = 1280
#define OFF_H2   17472    // 64 x 68   = 4352
#define OFF_WT   21824    // 4096 (16KB weight tile)
#define OFF_SRC  25920    // 64 int
#define OFF_DST  25984    // 64 int
#define OFF_NRM  26048    // 64 float
#define EDGE_SMEM_FLOATS 26112
#define EDGE_SMEM_BYTES  (EDGE_SMEM_FLOATS * 4)

__global__ __launch_bounds__(256, 2)
void edge_kernel(const float* __restrict__ hn, const float* __restrict__ he,
                 const float* __restrict__ pos, const float* __restrict__ fes,
                 const float* __restrict__ norm,
                 const int* __restrict__ esrc, const int* __restrict__ edst,
                 const float* __restrict__ ev_w1, const float* __restrict__ ev_w2,
                 const float* __restrict__ fc_w1, const float* __restrict__ fc_w2,
                 float* __restrict__ out_hen)
{
    extern __shared__ float sm[];
    float* sA   = sm + OFF_A;
    float* sF   = sm + OFF_F;
    float* sH1  = sm + OFF_H1;
    float* sV   = sm + OFF_V;
    float* sH2  = sm + OFF_H2;
    float* sWT  = sm + OFF_WT;
    int*   sSrc = (int*)(sm + OFF_SRC);
    int*   sDst = (int*)(sm + OFF_DST);
    float* sNrm = sm + OFF_NRM;

    const int tid = threadIdx.x;
    const int e0  = blockIdx.x * 64;

    if (tid < 64) {
        int ge = e0 + tid;
        sSrc[tid] = esrc[ge];
        sDst[tid] = edst[ge];
        sNrm[tid] = norm[ge];
    }
    __syncthreads();

    // ---- gather phase ----
    for (int i = tid; i < 64 * 96; i += 256) {
        int e = i / 96, k = i - e * 96;
        float v;
        if (k < 32)      v = he[(size_t)(e0 + e) * 32 + k];
        else if (k < 64) v = hn[(size_t)sSrc[e] * 32 + (k - 32)];
        else             v = hn[(size_t)sDst[e] * 32 + (k - 64)];
        sA[e * 97 + k] = v;
    }
    for (int i = tid; i < 64 * 24; i += 256) {
        int e = i / 24, k = i - e * 24;
        float v = 0.0f;
        if (k < 3)       v = pos[(size_t)sSrc[e] * 3 + k];
        else if (k < 6)  v = pos[(size_t)sDst[e] * 3 + (k - 3)];
        else if (k < 22) v = fes[(size_t)(e0 + e) * 16 + (k - 6)];
        sF[e * 24 + k] = v;
    }

    // ---- G1: H1 = relu(sA @ ev_w1)  (64x96 @ 96x128) ----
    {
        const int eg = tid >> 4, mg = tid & 15;
        const int el = eg * 4, m0 = mg * 8;
        float acc[4][8];
        #pragma unroll
        for (int i = 0; i < 4; i++)
            #pragma unroll
            for (int j = 0; j < 8; j++) acc[i][j] = 0.0f;

        for (int kt = 0; kt < 96; kt += 32) {
            __syncthreads();
            #pragma unroll
            for (int i = tid * 4; i < 4096; i += 1024)
                *(float4*)&sWT[i] = *(const float4*)&ev_w1[kt * 128 + i];
            __syncthreads();
            #pragma unroll 8
            for (int kk = 0; kk < 32; kk++) {
                float a0 = sA[(el + 0) * 97 + kt + kk];
                float a1 = sA[(el + 1) * 97 + kt + kk];
                float a2 = sA[(el + 2) * 97 + kt + kk];
                float a3 = sA[(el + 3) * 97 + kt + kk];
                float4 b0 = *(float4*)&sWT[kk * 128 + m0];
                float4 b1 = *(float4*)&sWT[kk * 128 + m0 + 4];
                float bb[8] = {b0.x, b0.y, b0.z, b0.w, b1.x, b1.y, b1.z, b1.w};
                #pragma unroll
                for (int j = 0; j < 8; j++) {
                    acc[0][j] += a0 * bb[j];
                    acc[1][j] += a1 * bb[j];
                    acc[2][j] += a2 * bb[j];
                    acc[3][j] += a3 * bb[j];
                }
            }
        }
        #pragma unroll
        for (int i = 0; i < 4; i++) {
            float4 r0 = make_float4(fmaxf(acc[i][0], 0.f), fmaxf(acc[i][1], 0.f),
                                    fmaxf(acc[i][2], 0.f), fmaxf(acc[i][3], 0.f));
            float4 r1 = make_float4(fmaxf(acc[i][4], 0.f), fmaxf(acc[i][5], 0.f),
                                    fmaxf(acc[i][6], 0.f), fmaxf(acc[i][7], 0.f));
            *(float4*)&sH1[(el + i) * 132 + m0]     = r0;
            *(float4*)&sH1[(el + i) * 132 + m0 + 4] = r1;
        }
    }

    // ---- G2: V = H1 @ ev_w2  (64x128 @ 128x16) ----
    {
        __syncthreads();
        #pragma unroll
        for (int i = tid * 4; i < 2048; i += 1024)
            *(float4*)&sWT[i] = *(const float4*)&ev_w2[i];
        __syncthreads();
        const int e = tid >> 2, m0 = (tid & 3) * 4;
        float a4[4] = {0.f, 0.f, 0.f, 0.f};
        #pragma unroll 8
        for (int k = 0; k < 128; k++) {
            float a = sH1[e * 132 + k];
            float4 b = *(float4*)&sWT[k * 16 + m0];
            a4[0] += a * b.x; a4[1] += a * b.y; a4[2] += a * b.z; a4[3] += a * b.w;
        }
        *(float4*)&sV[e * 20 + m0] = make_float4(a4[0], a4[1], a4[2], a4[3]);
    }

    // ---- G3: H2 = relu(sF @ fc_w1)  (64x22 @ 22x64) ----
    {
        __syncthreads();
        for (int i = tid; i < 22 * 64; i += 256) sWT[i] = fc_w1[i];
        __syncthreads();
        const int eg = tid >> 4, mg = tid & 15;
        const int el = eg * 4, m0 = mg * 4;
        float acc[4][4];
        #pragma unroll
        for (int i = 0; i < 4; i++)
            #pragma unroll
            for (int j = 0; j < 4; j++) acc[i][j] = 0.0f;
        #pragma unroll
        for (int k = 0; k < 22; k++) {
            float a0 = sF[(el + 0) * 24 + k];
            float a1 = sF[(el + 1) * 24 + k];
            float a2 = sF[(el + 2) * 24 + k];
            float a3 = sF[(el + 3) * 24 + k];
            float4 b = *(float4*)&sWT[k * 64 + m0];
            acc[0][0] += a0 * b.x; acc[0][1] += a0 * b.y; acc[0][2] += a0 * b.z; acc[0][3] += a0 * b.w;
            acc[1][0] += a1 * b.x; acc[1][1] += a1 * b.y; acc[1][2] += a1 * b.z; acc[1][3] += a1 * b.w;
            acc[2][0] += a2 * b.x; acc[2][1] += a2 * b.y; acc[2][2] += a2 * b.z; acc[2][3] += a2 * b.w;
            acc[3][0] += a3 * b.x; acc[3][1] += a3 * b.y; acc[3][2] += a3 * b.z; acc[3][3] += a3 * b.w;
        }
        #pragma unroll
        for (int i = 0; i < 4; i++) {
            float4 r = make_float4(fmaxf(acc[i][0], 0.f), fmaxf(acc[i][1], 0.f),
                                   fmaxf(acc[i][2], 0.f), fmaxf(acc[i][3], 0.f));
            *(float4*)&sH2[(el + i) * 68 + m0] = r;
        }
    }

    // ---- G4: tp = P @ fc_w2'  (64x1024 @ 1024x32), P on the fly ----
    {
        __syncthreads();   // sH2, sV complete; sWT free
        const int e = tid >> 2, m0 = (tid & 3) * 8;
        float vreg[16];
        #pragma unroll
        for (int v = 0; v < 16; v++) vreg[v] = sV[e * 20 + v];
        float acc[8];
        #pragma unroll
        for (int j = 0; j < 8; j++) acc[j] = 0.0f;

        for (int kt = 0; kt < 1024; kt += 128) {
            __syncthreads();
            #pragma unroll
            for (int i = tid * 4; i < 4096; i += 1024)
                *(float4*)&sWT[i] = *(const float4*)&fc_w2[kt * 32 + i];
            __syncthreads();
            const int k2b = kt >> 4;
            #pragma unroll 2
            for (int k2l = 0; k2l < 8; k2l++) {
                float h = sH2[e * 68 + k2b + k2l];
                #pragma unroll
                for (int v = 0; v < 16; v++) {
                    float a = h * vreg[v];
                    int kk = k2l * 16 + v;
                    float4 b0 = *(float4*)&sWT[kk * 32 + m0];
                    float4 b1 = *(float4*)&sWT[kk * 32 + m0 + 4];
                    acc[0] += a * b0.x; acc[1] += a * b0.y;
                    acc[2] += a * b0.z; acc[3] += a * b0.w;
                    acc[4] += a * b1.x; acc[5] += a * b1.y;
                    acc[6] += a * b1.z; acc[7] += a * b1.w;
                }
            }
        }

        // epilogue: hen = he + tp ; write out ; scatter-add hen*norm
        const int ge = e0 + e;
        float4 h0 = *(const float4*)&he[(size_t)ge * 32 + m0];
        float4 h1 = *(const float4*)&he[(size_t)ge * 32 + m0 + 4];
        float r[8];
        r[0] = h0.x + acc[0]; r[1] = h0.y + acc[1];
        r[2] = h0.z + acc[2]; r[3] = h0.w + acc[3];
        r[4] = h1.x + acc[4]; r[5] = h1.y + acc[5];
        r[6] = h1.z + acc[6]; r[7] = h1.w + acc[7];
        *(float4*)&out_hen[(size_t)ge * 32 + m0]     = make_float4(r[0], r[1], r[2], r[3]);
        *(float4*)&out_hen[(size_t)ge * 32 + m0 + 4] = make_float4(r[4], r[5], r[6], r[7]);

        const float nrm = sNrm[e];
        float* dp = &g_node_tmp[(size_t)sDst[e] * 32 + m0];
        #pragma unroll
        for (int j = 0; j < 8; j++) atomicAdd(dp + j, r[j] * nrm);
    }
}

// ---------------------------------------------------------------------------
// Node kernel: TN=64 nodes per block, 256 threads.
//   sX = [hn | node_tmp] (64x64), G5: relu(sX @ nu_w1) (64x128),
//   G6: @ nu_w2 (128x32), hnn = hn + out.
// ---------------------------------------------------------------------------
#define NOFF_X  0        // 64 x 68 = 4352
#define NOFF_H  4352     // 64 x 132 = 8448
#define NOFF_W  12800    // 8192 (32KB)
#define NODE_SMEM_FLOATS 20992
#define NODE_SMEM_BYTES  (NODE_SMEM_FLOATS * 4)

__global__ __launch_bounds__(256, 2)
void node_kernel(const float* __restrict__ hn,
                 const float* __restrict__ nu_w1, const float* __restrict__ nu_w2,
                 float* __restrict__ out_hnn)
{
    extern __shared__ float sm[];
    float* sX = sm + NOFF_X;
    float* sH = sm + NOFF_H;
    float* sW = sm + NOFF_W;
    const int tid = threadIdx.x;
    const int n0  = blockIdx.x * 64;

    for (int i = tid; i < 64 * 64; i += 256) {
        int e = i >> 6, k = i & 63;
        int gn = n0 + e;
        float v = 0.0f;
        if (gn < NNODES)
            v = (k < 32) ? hn[(size_t)gn * 32 + k] : g_node_tmp[(size_t)gn * 32 + (k - 32)];
        sX[e * 68 + k] = v;
    }
    #pragma unroll
    for (int i = tid * 4; i < 8192; i += 1024)
        *(float4*)&sW[i] = *(const float4*)&nu_w1[i];
    __syncthreads();

    // G5: relu(sX @ nu_w1)  (64x64 @ 64x128)
    {
        const int eg = tid >> 4, mg = tid & 15;
        const int el = eg * 4, m0 = mg * 8;
        float acc[4][8];
        #pragma unroll
        for (int i = 0; i < 4; i++)
            #pragma unroll
            for (int j = 0; j < 8; j++) acc[i][j] = 0.0f;
        #pragma unroll 4
        for (int k = 0; k < 64; k++) {
            float a0 = sX[(el + 0) * 68 + k];
            float a1 = sX[(el + 1) * 68 + k];
            float a2 = sX[(el + 2) * 68 + k];
            float a3 = sX[(el + 3) * 68 + k];
            float4 b0 = *(float4*)&sW[k * 128 + m0];
            float4 b1 = *(float4*)&sW[k * 128 + m0 + 4];
            float bb[8] = {b0.x, b0.y, b0.z, b0.w, b1.x, b1.y, b1.z, b1.w};
            #pragma unroll
            for (int j = 0; j < 8; j++) {
                acc[0][j] += a0 * bb[j];
                acc[1][j] += a1 * bb[j];
                acc[2][j] += a2 * bb[j];
                acc[3][j] += a3 * bb[j];
            }
        }
        #pragma unroll
        for (int i = 0; i < 4; i++) {
            float4 r0 = make_float4(fmaxf(acc[i][0], 0.f), fmaxf(acc[i][1], 0.f),
                                    fmaxf(acc[i][2], 0.f), fmaxf(acc[i][3], 0.f));
            float4 r1 = make_float4(fmaxf(acc[i][4], 0.f), fmaxf(acc[i][5], 0.f),
                                    fmaxf(acc[i][6], 0.f), fmaxf(acc[i][7], 0.f));
            *(float4*)&sH[(el + i) * 132 + m0]     = r0;
            *(float4*)&sH[(el + i) * 132 + m0 + 4] = r1;
        }
    }
    __syncthreads();
    #pragma unroll
    for (int i = tid * 4; i < 4096; i += 1024)
        *(float4*)&sW[i] = *(const float4*)&nu_w2[i];
    __syncthreads();

    // G6: (64x128 @ 128x32) + residual
    {
        const int e = tid >> 2, m0 = (tid & 3) * 8;
        float acc[8];
        #pragma unroll
        for (int j = 0; j < 8; j++) acc[j] = 0.0f;
        #pragma unroll 4
        for (int k = 0; k < 128; k++) {
            float a = sH[e * 132 + k];
            float4 b0 = *(float4*)&sW[k * 32 + m0];
            float4 b1 = *(float4*)&sW[k * 32 + m0 + 4];
            acc[0] += a * b0.x; acc[1] += a * b0.y;
            acc[2] += a * b0.z; acc[3] += a * b0.w;
            acc[4] += a * b1.x; acc[5] += a * b1.y;
            acc[6] += a * b1.z; acc[7] += a * b1.w;
        }
        const int gn = n0 + e;
        if (gn < NNODES) {
            float4 h0 = *(const float4*)&hn[(size_t)gn * 32 + m0];
            float4 h1 = *(const float4*)&hn[(size_t)gn * 32 + m0 + 4];
            *(float4*)&out_hnn[(size_t)gn * 32 + m0] =
                make_float4(h0.x + acc[0], h0.y + acc[1], h0.z + acc[2], h0.w + acc[3]);
            *(float4*)&out_hnn[(size_t)gn * 32 + m0 + 4] =
                make_float4(h1.x + acc[4], h1.y + acc[5], h1.z + acc[6], h1.w + acc[7]);
        }
    }
}

extern "C" void kernel_launch(void* const* d_in, const int* in_sizes, int n_in,
                              void* d_out, int out_size)
{
    const float* hn    = (const float*)d_in[0];
    const float* he    = (const float*)d_in[1];
    const float* pos   = (const float*)d_in[2];
    const float* fes   = (const float*)d_in[3];
    const float* norm  = (const float*)d_in[4];
    const int*   esrc  = (const int*)d_in[5];
    const int*   edst  = (const int*)d_in[6];
    const float* ev_w1 = (const float*)d_in[7];
    const float* ev_w2 = (const float*)d_in[8];
    const float* fc_w1 = (const float*)d_in[9];
    const float* fc_w2 = (const float*)d_in[10];
    const float* nu_w1 = (const float*)d_in[11];
    const float* nu_w2 = (const float*)d_in[12];

    float* out     = (float*)d_out;
    float* out_hnn = out;                               // [N, 32]
    float* out_hen = out + (size_t)NNODES * 32;         // [E, 32]

    cudaFuncSetAttribute(edge_kernel, cudaFuncAttributeMaxDynamicSharedMemorySize,
                         EDGE_SMEM_BYTES);
    cudaFuncSetAttribute(node_kernel, cudaFuncAttributeMaxDynamicSharedMemorySize,
                         NODE_SMEM_BYTES);

    zero_tmp_kernel<<<(NNODES * DD + 255) / 256, 256>>>();
    edge_kernel<<<NEDGES / 64, 256, EDGE_SMEM_BYTES>>>(
        hn, he, pos, fes, norm, esrc, edst,
        ev_w1, ev_w2, fc_w1, fc_w2, out_hen);
    node_kernel<<<(NNODES + 63) / 64, 256, NODE_SMEM_BYTES>>>(
        hn, nu_w1, nu_w2, out_hnn);
}

// round 5
// speedup vs baseline: 2.5059x; 2.5042x over previous
#include <cuda_runtime.h>
#include <cstdint>

#define NNODES 50000
#define NEDGES 800000

__device__ float g_node_tmp[NNODES * 32];

__global__ void zero_tmp_kernel() {
    int i = blockIdx.x * blockDim.x + threadIdx.x;
    if (i < NNODES * 32) g_node_tmp[i] = 0.0f;
}

// tf32 round (rna) applied once at staging
__device__ __forceinline__ float tf(float f) {
    uint32_t r; asm("cvt.rna.tf32.f32 %0, %1;" : "=r"(r) : "f"(f));
    return __uint_as_float(r);
}

__device__ __forceinline__ void mma8(float& c0, float& c1, float& c2, float& c3,
                                     float a0, float a1, float a2, float a3,
                                     float b0, float b1) {
    asm volatile(
        "mma.sync.aligned.m16n8k8.row.col.f32.tf32.tf32.f32 "
        "{%0,%1,%2,%3},{%4,%5,%6,%7},{%8,%9},{%0,%1,%2,%3};"
        : "+f"(c0), "+f"(c1), "+f"(c2), "+f"(c3)
        : "r"(__float_as_uint(a0)), "r"(__float_as_uint(a1)),
          "r"(__float_as_uint(a2)), "r"(__float_as_uint(a3)),
          "r"(__float_as_uint(b0)), "r"(__float_as_uint(b1)));
}

// ---- smem layout (float offsets) ----
// region X (reused): [sA(128x100)=12800 | W1(96x132)=12672] -> H1(128x132)=16896 -> Wc dbuf 2x(256x36)=18432
#define OA    0
#define OW1   12800
#define OH1   0
#define OWC   0
#define OF    25472   // F: 128 x 28 (24 used)
#define OFW1  29056   // fc_w1: 24 x 68
#define OW2   30688   // ev_w2: 128 x 24 (16 used)
#define OH2   33760   // H2: 128 x 66 (64 used)
#define OV    42208   // V: 128 x 20 (16 used)
#define OSRC  44768
#define ODST  44896
#define ONRM  45024
#define EDGE_SMEM_FLOATS 45152
#define EDGE_SMEM_BYTES  (EDGE_SMEM_FLOATS * 4)

__global__ __launch_bounds__(256)
void edge_kernel(const float* __restrict__ hn, const float* __restrict__ he,
                 const float* __restrict__ pos, const float* __restrict__ fes,
                 const float* __restrict__ norm,
                 const int* __restrict__ esrc, const int* __restrict__ edst,
                 const float* __restrict__ ev_w1, const float* __restrict__ ev_w2,
                 const float* __restrict__ fc_w1, const float* __restrict__ fc_w2,
                 float* __restrict__ out_hen)
{
    extern __shared__ float sm[];
    float* sA  = sm + OA;
    float* sW1 = sm + OW1;
    float* sH1 = sm + OH1;
    float* sF  = sm + OF;
    float* sFW = sm + OFW1;
    float* sW2 = sm + OW2;
    float* sH2 = sm + OH2;
    float* sV  = sm + OV;
    int*   sSrc = (int*)(sm + OSRC);
    int*   sDst = (int*)(sm + ODST);
    float* sNrm = sm + ONRM;

    const int tid  = threadIdx.x;
    const int lane = tid & 31;
    const int g    = lane >> 2;     // 0..7
    const int t4   = lane & 3;      // 0..3
    const int eb   = (tid >> 5) * 16;
    const int e0   = blockIdx.x * 128;

    if (tid < 128) {
        int ge = e0 + tid;
        sSrc[tid] = esrc[ge];
        sDst[tid] = edst[ge];
        sNrm[tid] = norm[ge];
    }
    __syncthreads();

    // ---------------- staging (all tf32-rounded) ----------------
    for (int i = tid; i < 128 * 24; i += 256) {        // sA: 128x96, stride 100
        int e = i / 24, q = i - e * 24;
        int k0 = q * 4;
        float4 v;
        if (k0 < 32)      v = *(const float4*)&he[(size_t)(e0 + e) * 32 + k0];
        else if (k0 < 64) v = *(const float4*)&hn[(size_t)sSrc[e] * 32 + (k0 - 32)];
        else              v = *(const float4*)&hn[(size_t)sDst[e] * 32 + (k0 - 64)];
        *(float4*)&sA[e * 100 + k0] = make_float4(tf(v.x), tf(v.y), tf(v.z), tf(v.w));
    }
    for (int i = tid; i < 128 * 24; i += 256) {        // sF: 128x24, stride 28
        int e = i / 24, k = i - e * 24;
        float v = 0.0f;
        if (k < 3)       v = pos[(size_t)sSrc[e] * 3 + k];
        else if (k < 6)  v = pos[(size_t)sDst[e] * 3 + (k - 3)];
        else if (k < 22) v = fes[(size_t)(e0 + e) * 16 + (k - 6)];
        sF[e * 28 + k] = tf(v);
    }
    for (int i = tid; i < 96 * 128; i += 256) {        // W1: 96x128, stride 132
        int kk = i >> 7, n = i & 127;
        sW1[kk * 132 + n] = tf(ev_w1[kk * 128 + n]);
    }
    for (int i = tid; i < 24 * 64; i += 256) {         // fc_w1: 24x64 (pad), stride 68
        int kk = i >> 6, n = i & 63;
        sFW[kk * 68 + n] = (kk < 22) ? tf(fc_w1[kk * 64 + n]) : 0.0f;
    }
    for (int i = tid; i < 128 * 16; i += 256) {        // ev_w2: 128x16, stride 24
        int kk = i >> 4, n = i & 15;
        sW2[kk * 24 + n] = tf(ev_w2[kk * 16 + n]);
    }
    __syncthreads();

    // ---------------- G1: H1 = relu(A @ W1)  m16 x n128 x k96 per warp ----------------
    float c1[16][4];
    #pragma unroll
    for (int nt = 0; nt < 16; nt++)
        #pragma unroll
        for (int j = 0; j < 4; j++) c1[nt][j] = 0.0f;
    {
        const int r0 = (eb + g) * 100, r1 = (eb + g + 8) * 100;
        #pragma unroll
        for (int t = 0; t < 12; t++) {
            const int kc = t * 8;
            float a0 = sA[r0 + kc + t4];
            float a1 = sA[r1 + kc + t4];
            float a2 = sA[r0 + kc + t4 + 4];
            float a3 = sA[r1 + kc + t4 + 4];
            const float* bk0 = &sW1[(kc + t4) * 132 + g];
            const float* bk1 = &sW1[(kc + t4 + 4) * 132 + g];
            #pragma unroll
            for (int nt = 0; nt < 16; nt++) {
                mma8(c1[nt][0], c1[nt][1], c1[nt][2], c1[nt][3],
                     a0, a1, a2, a3, bk0[nt * 8], bk1[nt * 8]);
            }
        }
    }
    __syncthreads();   // A/W1 region dead everywhere; safe to overwrite with H1

    // store H1 (relu, tf32), warp-private rows
    {
        const int r0 = (eb + g) * 132, r1 = (eb + g + 8) * 132;
        #pragma unroll
        for (int nt = 0; nt < 16; nt++) {
            int col = nt * 8 + 2 * t4;
            *(float2*)&sH1[r0 + col] =
                make_float2(tf(fmaxf(c1[nt][0], 0.f)), tf(fmaxf(c1[nt][1], 0.f)));
            *(float2*)&sH1[r1 + col] =
                make_float2(tf(fmaxf(c1[nt][2], 0.f)), tf(fmaxf(c1[nt][3], 0.f)));
        }
    }

    // ---------------- G3: H2 = relu(F @ fc_w1)  m16 x n64 x k24 ----------------
    {
        float c3[8][4];
        #pragma unroll
        for (int nt = 0; nt < 8; nt++)
            #pragma unroll
            for (int j = 0; j < 4; j++) c3[nt][j] = 0.0f;
        const int r0 = (eb + g) * 28, r1 = (eb + g + 8) * 28;
        #pragma unroll
        for (int t = 0; t < 3; t++) {
            const int kc = t * 8;
            float a0 = sF[r0 + kc + t4];
            float a1 = sF[r1 + kc + t4];
            float a2 = sF[r0 + kc + t4 + 4];
            float a3 = sF[r1 + kc + t4 + 4];
            const float* bk0 = &sFW[(kc + t4) * 68 + g];
            const float* bk1 = &sFW[(kc + t4 + 4) * 68 + g];
            #pragma unroll
            for (int nt = 0; nt < 8; nt++) {
                mma8(c3[nt][0], c3[nt][1], c3[nt][2], c3[nt][3],
                     a0, a1, a2, a3, bk0[nt * 8], bk1[nt * 8]);
            }
        }
        const int h0 = (eb + g) * 66, h1 = (eb + g + 8) * 66;
        #pragma unroll
        for (int nt = 0; nt < 8; nt++) {
            int col = nt * 8 + 2 * t4;
            *(float2*)&sH2[h0 + col] =
                make_float2(tf(fmaxf(c3[nt][0], 0.f)), tf(fmaxf(c3[nt][1], 0.f)));
            *(float2*)&sH2[h1 + col] =
                make_float2(tf(fmaxf(c3[nt][2], 0.f)), tf(fmaxf(c3[nt][3], 0.f)));
        }
    }
    __syncwarp();      // H1 cross-lane visibility within warp

    // ---------------- G2: V = H1 @ ev_w2  m16 x n16 x k128 ----------------
    {
        float c2[2][4];
        #pragma unroll
        for (int nt = 0; nt < 2; nt++)
            #pragma unroll
            for (int j = 0; j < 4; j++) c2[nt][j] = 0.0f;
        const int r0 = (eb + g) * 132, r1 = (eb + g + 8) * 132;
        #pragma unroll
        for (int t = 0; t < 16; t++) {
            const int kc = t * 8;
            float a0 = sH1[r0 + kc + t4];
            float a1 = sH1[r1 + kc + t4];
            float a2 = sH1[r0 + kc + t4 + 4];
            float a3 = sH1[r1 + kc + t4 + 4];
            const float* bk0 = &sW2[(kc + t4) * 24 + g];
            const float* bk1 = &sW2[(kc + t4 + 4) * 24 + g];
            #pragma unroll
            for (int nt = 0; nt < 2; nt++) {
                mma8(c2[nt][0], c2[nt][1], c2[nt][2], c2[nt][3],
                     a0, a1, a2, a3, bk0[nt * 8], bk1[nt * 8]);
            }
        }
        const int v0 = (eb + g) * 20, v1 = (eb + g + 8) * 20;
        #pragma unroll
        for (int nt = 0; nt < 2; nt++) {
            int col = nt * 8 + 2 * t4;
            *(float2*)&sV[v0 + col] = make_float2(tf(c2[nt][0]), tf(c2[nt][1]));
            *(float2*)&sV[v1 + col] = make_float2(tf(c2[nt][2]), tf(c2[nt][3]));
        }
    }
    __syncthreads();   // all H1 reads done; Wc buffers may overwrite region X

    // stage fc_w2 chunk 0 (K rows 0..255), stride 36, dbuf slot 0
    #pragma unroll
    for (int j = tid; j < 2048; j += 256) {
        float4 t = *(const float4*)&fc_w2[(size_t)j * 4];
        *(float4*)&sm[OWC + (j >> 3) * 36 + (j & 7) * 4] =
            make_float4(tf(t.x), tf(t.y), tf(t.z), tf(t.w));
    }
    __syncthreads();

    // ---------------- G4: tp = P @ fc_w2  m16 x n32 x k1024 ----------------
    float c4[4][4];
    #pragma unroll
    for (int nt = 0; nt < 4; nt++)
        #pragma unroll
        for (int j = 0; j < 4; j++) c4[nt][j] = 0.0f;

    float vr[8];
    {
        const int v0 = (eb + g) * 20, v1 = (eb + g + 8) * 20;
        vr[0] = sV[v0 + t4];     vr[1] = sV[v0 + t4 + 4];
        vr[2] = sV[v0 + t4 + 8]; vr[3] = sV[v0 + t4 + 12];
        vr[4] = sV[v1 + t4];     vr[5] = sV[v1 + t4 + 4];
        vr[6] = sV[v1 + t4 + 8]; vr[7] = sV[v1 + t4 + 12];
    }
    const int h0base = (eb + g) * 66, h1base = (eb + g + 8) * 66;

    for (int c = 0; c < 4; c++) {
        // prefetch next chunk into other buffer (no sync needed until loop end)
        if (c < 3) {
            float* dst = sm + OWC + ((c + 1) & 1) * 9216;
            #pragma unroll
            for (int j = tid; j < 2048; j += 256) {
                float4 t = *(const float4*)&fc_w2[(size_t)(c + 1) * 8192 + (size_t)j * 4];
                *(float4*)&dst[(j >> 3) * 36 + (j & 7) * 4] =
                    make_float4(tf(t.x), tf(t.y), tf(t.z), tf(t.w));
            }
        }
        const float* Wc = sm + OWC + (c & 1) * 9216;
        float h0 = 0.f, h1 = 0.f;
        #pragma unroll
        for (int t = 0; t < 32; t++) {
            if ((t & 1) == 0) {
                h0 = sH2[h0base + c * 16 + (t >> 1)];
                h1 = sH2[h1base + c * 16 + (t >> 1)];
            }
            const int sel = (t & 1) * 2;
            float a0 = h0 * vr[sel];
            float a2 = h0 * vr[sel + 1];
            float a1 = h1 * vr[4 + sel];
            float a3 = h1 * vr[4 + sel + 1];
            const float* bk0 = &Wc[(t * 8 + t4) * 36 + g];
            const float* bk1 = &Wc[(t * 8 + t4 + 4) * 36 + g];
            #pragma unroll
            for (int nt = 0; nt < 4; nt++) {
                mma8(c4[nt][0], c4[nt][1], c4[nt][2], c4[nt][3],
                     a0, a1, a2, a3, bk0[nt * 8], bk1[nt * 8]);
            }
        }
        __syncthreads();
    }

    // ---------------- epilogue: residual, write hen, scatter ----------------
    #pragma unroll
    for (int r = 0; r < 2; r++) {
        const int e  = eb + g + 8 * r;
        const int ge = e0 + e;
        const float nrm = sNrm[e];
        float* ap = &g_node_tmp[(size_t)sDst[e] * 32];
        const float* hep = &he[(size_t)ge * 32];
        float* op = &out_hen[(size_t)ge * 32];
        #pragma unroll
        for (int nt = 0; nt < 4; nt++) {
            int col = nt * 8 + 2 * t4;
            float2 h = *(const float2*)&hep[col];
            float x0 = h.x + c4[nt][2 * r];
            float x1 = h.y + c4[nt][2 * r + 1];
            *(float2*)&op[col] = make_float2(x0, x1);
            atomicAdd(&ap[col],     x0 * nrm);
            atomicAdd(&ap[col + 1], x1 * nrm);
        }
    }
}

// ---------------- node kernel (SIMT fp32, exact) ----------------
#define NOFF_X  0
#define NOFF_H  4352
#define NOFF_W  12800
#define NODE_SMEM_BYTES (20992 * 4)

__global__ __launch_bounds__(256, 2)
void node_kernel(const float* __restrict__ hn,
                 const float* __restrict__ nu_w1, const float* __restrict__ nu_w2,
                 float* __restrict__ out_hnn)
{
    extern __shared__ float sm[];
    float* sX = sm + NOFF_X;
    float* sH = sm + NOFF_H;
    float* sW = sm + NOFF_W;
    const int tid = threadIdx.x;
    const int n0  = blockIdx.x * 64;

    for (int i = tid; i < 64 * 64; i += 256) {
        int e = i >> 6, k = i & 63;
        int gn = n0 + e;
        float v = 0.0f;
        if (gn < NNODES)
            v = (k < 32) ? hn[(size_t)gn * 32 + k] : g_node_tmp[(size_t)gn * 32 + (k - 32)];
        sX[e * 68 + k] = v;
    }
    #pragma unroll
    for (int i = tid * 4; i < 8192; i += 1024)
        *(float4*)&sW[i] = *(const float4*)&nu_w1[i];
    __syncthreads();

    {
        const int eg = tid >> 4, mg = tid & 15;
        const int el = eg * 4, m0 = mg * 8;
        float acc[4][8];
        #pragma unroll
        for (int i = 0; i < 4; i++)
            #pragma unroll
            for (int j = 0; j < 8; j++) acc[i][j] = 0.0f;
        #pragma unroll 4
        for (int k = 0; k < 64; k++) {
            float a0 = sX[(el + 0) * 68 + k];
            float a1 = sX[(el + 1) * 68 + k];
            float a2 = sX[(el + 2) * 68 + k];
            float a3 = sX[(el + 3) * 68 + k];
            float4 b0 = *(float4*)&sW[k * 128 + m0];
            float4 b1 = *(float4*)&sW[k * 128 + m0 + 4];
            float bb[8] = {b0.x, b0.y, b0.z, b0.w, b1.x, b1.y, b1.z, b1.w};
            #pragma unroll
            for (int j = 0; j < 8; j++) {
                acc[0][j] += a0 * bb[j];
                acc[1][j] += a1 * bb[j];
                acc[2][j] += a2 * bb[j];
                acc[3][j] += a3 * bb[j];
            }
        }
        #pragma unroll
        for (int i = 0; i < 4; i++) {
            float4 r0 = make_float4(fmaxf(acc[i][0], 0.f), fmaxf(acc[i][1], 0.f),
                                    fmaxf(acc[i][2], 0.f), fmaxf(acc[i][3], 0.f));
            float4 r1 = make_float4(fmaxf(acc[i][4], 0.f), fmaxf(acc[i][5], 0.f),
                                    fmaxf(acc[i][6], 0.f), fmaxf(acc[i][7], 0.f));
            *(float4*)&sH[(el + i) * 132 + m0]     = r0;
            *(float4*)&sH[(el + i) * 132 + m0 + 4] = r1;
        }
    }
    __syncthreads();
    #pragma unroll
    for (int i = tid * 4; i < 4096; i += 1024)
        *(float4*)&sW[i] = *(const float4*)&nu_w2[i];
    __syncthreads();

    {
        const int e = tid >> 2, m0 = (tid & 3) * 8;
        float acc[8];
        #pragma unroll
        for (int j = 0; j < 8; j++) acc[j] = 0.0f;
        #pragma unroll 4
        for (int k = 0; k < 128; k++) {
            float a = sH[e * 132 + k];
            float4 b0 = *(float4*)&sW[k * 32 + m0];
            float4 b1 = *(float4*)&sW[k * 32 + m0 + 4];
            acc[0] += a * b0.x; acc[1] += a * b0.y;
            acc[2] += a * b0.z; acc[3] += a * b0.w;
            acc[4] += a * b1.x; acc[5] += a * b1.y;
            acc[6] += a * b1.z; acc[7] += a * b1.w;
        }
        const int gn = n0 + e;
        if (gn < NNODES) {
            float4 h0 = *(const float4*)&hn[(size_t)gn * 32 + m0];
            float4 h1 = *(const float4*)&hn[(size_t)gn * 32 + m0 + 4];
            *(float4*)&out_hnn[(size_t)gn * 32 + m0] =
                make_float4(h0.x + acc[0], h0.y + acc[1], h0.z + acc[2], h0.w + acc[3]);
            *(float4*)&out_hnn[(size_t)gn * 32 + m0 + 4] =
                make_float4(h1.x + acc[4], h1.y + acc[5], h1.z + acc[6], h1.w + acc[7]);
        }
    }
}

extern "C" void kernel_launch(void* const* d_in, const int* in_sizes, int n_in,
                              void* d_out, int out_size)
{
    const float* hn    = (const float*)d_in[0];
    const float* he    = (const float*)d_in[1];
    const float* pos   = (const float*)d_in[2];
    const float* fes   = (const float*)d_in[3];
    const float* norm  = (const float*)d_in[4];
    const int*   esrc  = (const int*)d_in[5];
    const int*   edst  = (const int*)d_in[6];
    const float* ev_w1 = (const float*)d_in[7];
    const float* ev_w2 = (const float*)d_in[8];
    const float* fc_w1 = (const float*)d_in[9];
    const float* fc_w2 = (const float*)d_in[10];
    const float* nu_w1 = (const float*)d_in[11];
    const float* nu_w2 = (const float*)d_in[12];

    float* out     = (float*)d_out;
    float* out_hnn = out;                          // [N, 32]
    float* out_hen = out + (size_t)NNODES * 32;    // [E, 32]

    cudaFuncSetAttribute(edge_kernel, cudaFuncAttributeMaxDynamicSharedMemorySize,
                         EDGE_SMEM_BYTES);
    cudaFuncSetAttribute(node_kernel, cudaFuncAttributeMaxDynamicSharedMemorySize,
                         NODE_SMEM_BYTES);

    zero_tmp_kernel<<<(NNODES * 32 + 255) / 256, 256>>>();
    edge_kernel<<<NEDGES / 128, 256, EDGE_SMEM_BYTES>>>(
        hn, he, pos, fes, norm, esrc, edst,
        ev_w1, ev_w2, fc_w1, fc_w2, out_hen);
    node_kernel<<<(NNODES + 63) / 64, 256, NODE_SMEM_BYTES>>>(
        hn, nu_w1, nu_w2, out_hnn);
}